// round 15
// baseline (speedup 1.0000x reference)
#include <cuda_runtime.h>
#include <cuda_fp16.h>
#include <math.h>
#include <stdint.h>

// Problem shapes (fixed by reference)
#define T_STEPS 512
#define BATCH   256
#define NIN     1024
#define NH      1024
#define M_TOTAL (T_STEPS * BATCH)   // 131072

// ============================================================================
// Device scratch (static — no allocation allowed)
// ============================================================================
__device__ __half g_A16[(size_t)M_TOTAL * NIN];          // inputs fp16, [M][K]
__device__ __half g_Wxh16[(size_t)NH * NIN];             // W_xh^T fp16, [N][K]
__device__ __half g_Whh16[(size_t)NH * NH];              // W_hh^T fp16, [N][K]
__device__ __half g_H16[2][(size_t)BATCH * NH];          // state fp16, double buffered

// ============================================================================
// PTX helpers (sm_90-baseline or older: compile for plain compute_103)
// ============================================================================
__device__ __forceinline__ uint32_t smem_u32(const void* p) {
    uint32_t a;
    asm("{ .reg .u64 t; cvta.to.shared.u64 t, %1; cvt.u32.u64 %0, t; }"
        : "=r"(a) : "l"(p));
    return a;
}

#define CP16(dst, src) \
    asm volatile("cp.async.cg.shared.global [%0], [%1], 16;" :: "r"(dst), "l"(src))
#define CP_COMMIT() asm volatile("cp.async.commit_group;" ::: "memory")
#define CP_WAIT(n)  asm volatile("cp.async.wait_group %0;" :: "n"(n) : "memory")

#define CLUSTER_ARRIVE() \
    asm volatile("barrier.cluster.arrive.aligned;" ::: "memory")
#define CLUSTER_WAIT() \
    asm volatile("barrier.cluster.wait.aligned;" ::: "memory")

__device__ __forceinline__ void ldsm4(uint32_t r[4], uint32_t addr) {
    asm volatile("ldmatrix.sync.aligned.m8n8.x4.shared.b16 {%0,%1,%2,%3}, [%4];"
                 : "=r"(r[0]), "=r"(r[1]), "=r"(r[2]), "=r"(r[3]) : "r"(addr));
}

__device__ __forceinline__ void mma_f16(float c[4], const uint32_t a[4],
                                        const uint32_t b[2]) {
    asm volatile(
        "mma.sync.aligned.m16n8k16.row.col.f32.f16.f16.f32 "
        "{%0,%1,%2,%3}, {%4,%5,%6,%7}, {%8,%9}, {%0,%1,%2,%3};"
        : "+f"(c[0]), "+f"(c[1]), "+f"(c[2]), "+f"(c[3])
        : "r"(a[0]), "r"(a[1]), "r"(a[2]), "r"(a[3]), "r"(b[0]), "r"(b[1]));
}

#define PK_CTAS  128
#define PK_CLUSTER 16   // CTAs per cluster = one m-group

// Dense 2048B-row layout with XOR swizzle (persist kernel W/H slices).
__device__ __forceinline__ uint32_t swz(int row, int gseg) {
    return (uint32_t)(row * 2048 + (gseg >> 3) * 128 + (((gseg ^ row) & 7) * 16));
}
// Dense 128B-row layout with XOR swizzle (gemm1 K64 chunks). seg 0..7.
__device__ __forceinline__ uint32_t sw128(int row, int seg) {
    return (uint32_t)(row * 128 + (((seg ^ row) & 7) * 16));
}

// ============================================================================
// Prep: transpose a weight [K][N] fp32 -> [N][K] fp16
// ============================================================================
__global__ __launch_bounds__(256) void conv_w16_kernel(const float* __restrict__ W,
                                                       int which)
{
    __shared__ float tile[32][33];
    __half* out16 = which ? g_Whh16 : g_Wxh16;
    const int bx = blockIdx.x * 32;   // n block
    const int by = blockIdx.y * 32;   // k block
    const int tx = threadIdx.x & 31;
    const int ty = threadIdx.x >> 5;
    for (int i = ty; i < 32; i += 8)
        tile[i][tx] = W[(size_t)(by + i) * NH + bx + tx];
    __syncthreads();
    for (int i = ty; i < 32; i += 8) {
        float x = tile[tx][i];                 // W[by+tx][bx+i]
        out16[(size_t)(bx + i) * NIN + by + tx] = __float2half(x);
    }
}

// ============================================================================
// Prep: inputs fp32 [M][K] -> g_A16 fp16 (same layout)
// ============================================================================
__global__ __launch_bounds__(256) void conv_a_kernel(const float* __restrict__ A)
{
    const size_t n4 = (size_t)M_TOTAL * NIN / 4;
    size_t i = (size_t)blockIdx.x * blockDim.x + threadIdx.x;
    const size_t stride = (size_t)gridDim.x * blockDim.x;
    for (; i < n4; i += stride) {
        float4 v = ((const float4*)A)[i];
        ((__half2*)g_A16)[i * 2 + 0] = __floats2half2_rn(v.x, v.y);
        ((__half2*)g_A16)[i * 2 + 1] = __floats2half2_rn(v.z, v.w);
    }
}

// ============================================================================
// Phase 1 GEMM: C[M,N] = A16 @ W16^T + bias  (single-term fp16 HMMA)
// CTA 128m x 256n, 512 thr (16 warps 2x8, warp tile 64x32), K-chunk 64,
// 3 stages, dense 128B rows + XOR swizzle.  (R14 configuration — unchanged.)
// ============================================================================
#define G1A_B    16384
#define G1_STAGE 49152
#define G1_SMEM  147456

__global__ __launch_bounds__(512, 1) void gemm1_kernel(
    const float* __restrict__ bias, float* __restrict__ C)
{
    extern __shared__ char smem[];
    const uint32_t sb0 = smem_u32(smem);
    const int tid  = threadIdx.x;
    const int wid  = tid >> 5;
    const int lane = tid & 31;
    const int m0 = blockIdx.y * 128;
    const int n0 = blockIdx.x * 256;
    const int warp_m = (wid >> 3) * 64;   // 0 or 64
    const int warp_n = (wid & 7) * 32;    // 0..224

    float acc[4][4][4];
#pragma unroll
    for (int i = 0; i < 4; i++)
#pragma unroll
        for (int j = 0; j < 4; j++)
#pragma unroll
            for (int k = 0; k < 4; k++) acc[i][j][k] = 0.f;

    auto issue = [&](int c, int s) {
        const uint32_t st = sb0 + s * G1_STAGE;
        const int kbase = c * 64;
#pragma unroll
        for (int i = 0; i < 6; i++) {
            const int idx = tid + i * 512;
            if (idx < 1024) {
                const int row = idx >> 3, seg = idx & 7;
                CP16(st + sw128(row, seg),
                     g_A16 + (size_t)(m0 + row) * NIN + kbase + seg * 8);
            } else {
                const int j = idx - 1024;
                const int row = j >> 3, seg = j & 7;
                CP16(st + G1A_B + sw128(row, seg),
                     g_Wxh16 + (size_t)(n0 + row) * NIN + kbase + seg * 8);
            }
        }
    };

    issue(0, 0); CP_COMMIT();
    issue(1, 1); CP_COMMIT();

    for (int it = 0; it < 16; it++) {
        CP_WAIT(1);
        __syncthreads();
        if (it + 2 < 16) issue(it + 2, (it + 2) % 3);
        CP_COMMIT();

        const uint32_t st = sb0 + (it % 3) * G1_STAGE;
#pragma unroll
        for (int ks = 0; ks < 4; ks++) {
            uint32_t ah[4][4];
#pragma unroll
            for (int mt = 0; mt < 4; mt++) {
                const int row = warp_m + mt * 16 + (lane & 15);
                const int seg = ks * 2 + (lane >> 4);
                ldsm4(ah[mt], st + sw128(row, seg));
            }
            uint32_t bh[4][2];
#pragma unroll
            for (int g = 0; g < 2; g++) {
                const int row = warp_n + g * 16 + (lane & 7) + ((lane >> 4) << 3);
                const int seg = ks * 2 + ((lane >> 3) & 1);
                uint32_t t[4];
                ldsm4(t, st + G1A_B + sw128(row, seg));
                bh[g * 2][0] = t[0]; bh[g * 2][1] = t[1];
                bh[g * 2 + 1][0] = t[2]; bh[g * 2 + 1][1] = t[3];
            }
#pragma unroll
            for (int mt = 0; mt < 4; mt++)
#pragma unroll
                for (int nt = 0; nt < 4; nt++)
                    mma_f16(acc[mt][nt], ah[mt], bh[nt]);
        }
    }

#pragma unroll
    for (int mt = 0; mt < 4; mt++) {
        const int m = m0 + warp_m + mt * 16 + (lane >> 2);
#pragma unroll
        for (int nt = 0; nt < 4; nt++) {
            const int n = n0 + warp_n + nt * 8 + (lane & 3) * 2;
            const float b0 = bias[n], b1 = bias[n + 1];
            float2 v0 = make_float2(acc[mt][nt][0] + b0, acc[mt][nt][1] + b1);
            float2 v1 = make_float2(acc[mt][nt][2] + b0, acc[mt][nt][3] + b1);
            *(float2*)(C + (size_t)m * NH + n)       = v0;
            *(float2*)(C + (size_t)(m + 8) * NH + n) = v1;
        }
    }
}

// ============================================================================
// t = 0: h0 = tanh(xw[0]); write fp32 out[0] and fp16 state buf 0
// ============================================================================
__global__ __launch_bounds__(256) void tanh0_kernel(float* __restrict__ x)
{
    const size_t i = (size_t)blockIdx.x * blockDim.x + threadIdx.x;  // float4 idx
    float4 v = ((const float4*)x)[i];
    v.x = tanhf(v.x); v.y = tanhf(v.y); v.z = tanhf(v.z); v.w = tanhf(v.w);
    ((float4*)x)[i] = v;
    ((__half2*)g_H16[0])[i * 2 + 0] = __floats2half2_rn(v.x, v.y);
    ((__half2*)g_H16[0])[i * 2 + 1] = __floats2half2_rn(v.z, v.w);
}

// ============================================================================
// Persistent RNN recurrence: t = 1..511.
// Grid 128 CTAs, CLUSTER SIZE 16: each cluster = one m-group (32 batch rows),
// 16 n-blocks (64 cols each). HW barrier.cluster replaces the L2 spin barrier.
// W_hh slice (64 rows x 1024 fp16 = 128 KB) resident, dense swizzled rows.
// H slice (32 x 1024 = 64 KB) loaded per step in 4 progressive commit groups.
// Split-K across warps (kh = wid>>2); warp tile 16m x 32n.
// Epilogue split: each warp of a kh-pair finalizes 8 of the 16 rows.
// smem: W [0,131072) | H [131072,196608) | rbuf [196608,204800)
// ============================================================================
#define PW_BASE  0
#define PH_BASE  131072
#define PR_BASE  196608
#define PK_SMEM  204800

__global__ __launch_bounds__(256, 1) void rnn_persist_kernel(float* __restrict__ out)
{
    extern __shared__ char smem[];
    const uint32_t sb = smem_u32(smem);
    const int tid  = threadIdx.x;
    const int wid  = tid >> 5;
    const int lane = tid & 31;
    const int mb = blockIdx.x >> 4;    // 0..7  (m-group == cluster)
    const int nb = blockIdx.x & 15;    // 0..15
    const int m0 = mb * 32;
    const int n0 = nb * 64;
    const int warp_m = (wid & 1) * 16;        // 0 or 16
    const int warp_n = ((wid >> 1) & 1) * 32; // 0 or 32
    const int kh     = wid >> 2;              // k16 half within each k32 sub

    // ---- Load resident W_hh slice: 64 rows x 128 gsegs, swizzled ----
    for (int idx = tid; idx < 8192; idx += 256) {
        const int r    = idx >> 7;        // 0..63
        const int gseg = idx & 127;       // 0..127
        CP16(sb + PW_BASE + swz(r, gseg),
             g_Whh16 + (size_t)(n0 + r) * NH + gseg * 8);
    }
    CP_COMMIT(); CP_WAIT(0); __syncthreads();

    const int hrow = tid >> 3;   // 0..31
    const int hsb  = tid & 7;    // seg base

    for (int t = 1; t < T_STEPS; t++) {
        const __half* Hh = g_H16[(t - 1) & 1];
        __half* HO = g_H16[t & 1];
        float* X = out + (size_t)t * BATCH * NH;

        // ---- Issue the H slice: 4 progressive commit groups of 16 KB ----
        const __half* hsrc = Hh + (size_t)(m0 + hrow) * NH;
        const uint32_t hdst = sb + PH_BASE;
#pragma unroll
        for (int g = 0; g < 4; g++) {
#pragma unroll
            for (int j = 0; j < 4; j++) {
                const int gseg = g * 32 + hsb + j * 8;
                CP16(hdst + swz(hrow, gseg), hsrc + gseg * 8);
            }
            CP_COMMIT();
        }

        // Prefetch this warp's OWN half-rows of the xw tile while H streams
        float2 xwr[4];
        {
            const int mrow = m0 + warp_m + (lane >> 2) + kh * 8;
#pragma unroll
            for (int nt = 0; nt < 4; nt++) {
                const int n = n0 + warp_n + nt * 8 + (lane & 3) * 2;
                xwr[nt] = *(const float2*)(X + (size_t)mrow * NH + n);
            }
        }

        float acc[4][4];
#pragma unroll
        for (int i = 0; i < 4; i++)
#pragma unroll
            for (int j = 0; j < 4; j++) acc[i][j] = 0.f;

        // ---- Compute: subs 8g..8g+7 unlock after commit group g lands ----
        const int arow = warp_m + (lane & 15);
#pragma unroll
        for (int sub = 0; sub < 32; sub++) {
            if (sub == 0)  { CP_WAIT(3); __syncthreads(); }
            if (sub == 8)  { CP_WAIT(2); __syncthreads(); }
            if (sub == 16) { CP_WAIT(1); __syncthreads(); }
            if (sub == 24) { CP_WAIT(0); __syncthreads(); }

            const int gsA = sub * 4 + kh * 2 + (lane >> 4);
            uint32_t ah[4];
            ldsm4(ah, sb + PH_BASE + swz(arow, gsA));

            const int gsB = sub * 4 + kh * 2 + ((lane >> 3) & 1);
            uint32_t bh[4][2];
#pragma unroll
            for (int g = 0; g < 2; g++) {
                const int nr = warp_n + g * 16 + (lane & 7) + ((lane >> 4) << 3);
                uint32_t tmp[4];
                ldsm4(tmp, sb + PW_BASE + swz(nr, gsB));
                bh[g * 2][0] = tmp[0]; bh[g * 2][1] = tmp[1];
                bh[g * 2 + 1][0] = tmp[2]; bh[g * 2 + 1][1] = tmp[3];
            }
#pragma unroll
            for (int nt = 0; nt < 4; nt++) mma_f16(acc[nt], ah, bh[nt]);
        }

        // ---- Exchange the NON-owned half of each warp's accumulators ----
        __syncthreads();
        float* rbuf = (float*)(smem + PR_BASE);   // 32 x 64 fp32 = 8 KB
        {
            const int exh = kh ^ 1;   // the half this warp gives away
            const int m = warp_m + (lane >> 2) + exh * 8;
#pragma unroll
            for (int nt = 0; nt < 4; nt++) {
                const int n = warp_n + nt * 8 + (lane & 3) * 2;
                *(float2*)(rbuf + m * 64 + n) = make_float2(
                    acc[nt][exh * 2 + 0], acc[nt][exh * 2 + 1]);
            }
        }
        __syncthreads();

        // ---- Epilogue (ALL warps): finalize own half (8 rows each) ----
        {
            const int mloc = warp_m + (lane >> 2) + kh * 8;
            const int m = m0 + mloc;
#pragma unroll
            for (int nt = 0; nt < 4; nt++) {
                const int nloc = warp_n + nt * 8 + (lane & 3) * 2;
                const int n = n0 + nloc;
                const size_t off = (size_t)m * NH + n;
                const float2 other = *(const float2*)(rbuf + mloc * 64 + nloc);
                const float s0 = acc[nt][kh * 2 + 0] + other.x;
                const float s1 = acc[nt][kh * 2 + 1] + other.y;
                const float v0 = tanhf(xwr[nt].x + s0);
                const float v1 = tanhf(xwr[nt].y + s1);
                *(float2*)(X + off) = make_float2(v0, v1);
                *(__half2*)(HO + off) = __floats2half2_rn(v0, v1);
                if (t == T_STEPS - 1)
                    *(float2*)(out + (size_t)T_STEPS * BATCH * NH + off) =
                        make_float2(v0, v1);
            }
        }

        // ---- HW cluster barrier between steps (release/acquire) ----
        CLUSTER_ARRIVE();
        CLUSTER_WAIT();
    }
}

// ============================================================================
// Launch
// ============================================================================
extern "C" void kernel_launch(void* const* d_in, const int* in_sizes, int n_in,
                              void* d_out, int out_size)
{
    const float* inputs = (const float*)d_in[0];   // [T, B, NIN]
    const float* W_xh   = (const float*)d_in[1];   // [NIN, NH]
    const float* W_hh   = (const float*)d_in[2];   // [NH, NH]
    const float* b_h    = (const float*)d_in[3];   // [NH]
    float* out = (float*)d_out;                    // [T, B, NH] + [B, NH]

    const size_t step_elems = (size_t)BATCH * NH;  // 262144

    static bool attr_set = false;
    if (!attr_set) {
        cudaFuncSetAttribute(gemm1_kernel,
                             cudaFuncAttributeMaxDynamicSharedMemorySize, G1_SMEM);
        cudaFuncSetAttribute(rnn_persist_kernel,
                             cudaFuncAttributeMaxDynamicSharedMemorySize, PK_SMEM);
        cudaFuncSetAttribute(rnn_persist_kernel,
                             cudaFuncAttributeNonPortableClusterSizeAllowed, 1);
        attr_set = true;
    }

    // Prep: transpose weights to fp16 [N][K]; convert inputs to fp16
    {
        dim3 grid(NH / 32, NIN / 32);
        conv_w16_kernel<<<grid, 256>>>(W_xh, 0);
        conv_w16_kernel<<<grid, 256>>>(W_hh, 1);
        conv_a_kernel<<<8192, 256>>>(inputs);
    }

    // Phase 1: xw = inputs @ W_xh + b_h  -> out[0..T)
    {
        dim3 grid(NH / 256, M_TOTAL / 128);   // (4, 1024)
        gemm1_kernel<<<grid, 512, G1_SMEM>>>(b_h, out);
    }

    // t = 0
    tanh0_kernel<<<(int)(step_elems / 4 / 256), 256>>>(out);

    // t = 1..T-1 in ONE persistent kernel with 16-CTA clusters (one per m-group)
    {
        cudaLaunchConfig_t cfg = {};
        cfg.gridDim = dim3(PK_CTAS, 1, 1);
        cfg.blockDim = dim3(256, 1, 1);
        cfg.dynamicSmemBytes = PK_SMEM;
        static cudaLaunchAttribute attrs[1];
        attrs[0].id = cudaLaunchAttributeClusterDimension;
        attrs[0].val.clusterDim.x = PK_CLUSTER;
        attrs[0].val.clusterDim.y = 1;
        attrs[0].val.clusterDim.z = 1;
        cfg.attrs = attrs;
        cfg.numAttrs = 1;
        cudaLaunchKernelEx(&cfg, rnn_persist_kernel, out);
    }
}

// round 16
// speedup vs baseline: 1.4432x; 1.4432x over previous
#include <cuda_runtime.h>
#include <cuda_fp16.h>
#include <math.h>
#include <stdint.h>

// Problem shapes (fixed by reference)
#define T_STEPS 512
#define BATCH   256
#define NIN     1024
#define NH      1024
#define M_TOTAL (T_STEPS * BATCH)   // 131072

// ============================================================================
// Device scratch (static — no allocation allowed)
// ============================================================================
__device__ __half g_A16[(size_t)M_TOTAL * NIN];          // inputs fp16, [M][K]
__device__ __half g_Wxh16[(size_t)NH * NIN];             // W_xh^T fp16, [N][K]
__device__ __half g_Whh16[(size_t)NH * NH];              // W_hh^T fp16, [N][K]
__device__ __half g_H16[2][(size_t)BATCH * NH];          // state fp16, double buffered

// Per-m-group barrier state (8 groups of 16 CTAs); zero-init, phase monotonic
__device__ unsigned g_bar_count[8];
__device__ unsigned g_bar_phase[8];

// ============================================================================
// PTX helpers (all sm_80-era: compile for plain compute_103)
// ============================================================================
__device__ __forceinline__ uint32_t smem_u32(const void* p) {
    uint32_t a;
    asm("{ .reg .u64 t; cvta.to.shared.u64 t, %1; cvt.u32.u64 %0, t; }"
        : "=r"(a) : "l"(p));
    return a;
}

#define CP16(dst, src) \
    asm volatile("cp.async.cg.shared.global [%0], [%1], 16;" :: "r"(dst), "l"(src))
#define CP_COMMIT() asm volatile("cp.async.commit_group;" ::: "memory")
#define CP_WAIT(n)  asm volatile("cp.async.wait_group %0;" :: "n"(n) : "memory")

__device__ __forceinline__ void ldsm4(uint32_t r[4], uint32_t addr) {
    asm volatile("ldmatrix.sync.aligned.m8n8.x4.shared.b16 {%0,%1,%2,%3}, [%4];"
                 : "=r"(r[0]), "=r"(r[1]), "=r"(r[2]), "=r"(r[3]) : "r"(addr));
}

__device__ __forceinline__ void mma_f16(float c[4], const uint32_t a[4],
                                        const uint32_t b[2]) {
    asm volatile(
        "mma.sync.aligned.m16n8k16.row.col.f32.f16.f16.f32 "
        "{%0,%1,%2,%3}, {%4,%5,%6,%7}, {%8,%9}, {%0,%1,%2,%3};"
        : "+f"(c[0]), "+f"(c[1]), "+f"(c[2]), "+f"(c[3])
        : "r"(a[0]), "r"(a[1]), "r"(a[2]), "r"(a[3]), "r"(b[0]), "r"(b[1]));
}

__device__ __forceinline__ unsigned ld_acq(const unsigned* p) {
    unsigned v;
    asm volatile("ld.acquire.gpu.global.u32 %0, [%1];" : "=r"(v) : "l"(p) : "memory");
    return v;
}
__device__ __forceinline__ void st_rel(unsigned* p, unsigned v) {
    asm volatile("st.release.gpu.global.u32 [%0], %1;" :: "l"(p), "r"(v) : "memory");
}

#define PK_CTAS  128
#define PK_GROUP 16   // CTAs per m-group barrier

__device__ __forceinline__ void grid_bar(int g) {
    unsigned ph = ld_acq(&g_bar_phase[g]);
    __threadfence();
    unsigned old = atomicAdd(&g_bar_count[g], 1);
    if (old == PK_GROUP - 1) {
        g_bar_count[g] = 0;
        st_rel(&g_bar_phase[g], ph + 1);
    } else {
        while (ld_acq(&g_bar_phase[g]) == ph) { }
    }
}

// Dense 2048B-row layout with XOR swizzle (persist kernel W/H slices).
__device__ __forceinline__ uint32_t swz(int row, int gseg) {
    return (uint32_t)(row * 2048 + (gseg >> 3) * 128 + (((gseg ^ row) & 7) * 16));
}
// Dense 128B-row layout with XOR swizzle (gemm1 K64 chunks). seg 0..7.
__device__ __forceinline__ uint32_t sw128(int row, int seg) {
    return (uint32_t)(row * 128 + (((seg ^ row) & 7) * 16));
}

// ============================================================================
// Prep: transpose a weight [K][N] fp32 -> [N][K] fp16
// ============================================================================
__global__ __launch_bounds__(256) void conv_w16_kernel(const float* __restrict__ W,
                                                       int which)
{
    __shared__ float tile[32][33];
    __half* out16 = which ? g_Whh16 : g_Wxh16;
    const int bx = blockIdx.x * 32;   // n block
    const int by = blockIdx.y * 32;   // k block
    const int tx = threadIdx.x & 31;
    const int ty = threadIdx.x >> 5;
    for (int i = ty; i < 32; i += 8)
        tile[i][tx] = W[(size_t)(by + i) * NH + bx + tx];
    __syncthreads();
    for (int i = ty; i < 32; i += 8) {
        float x = tile[tx][i];                 // W[by+tx][bx+i]
        out16[(size_t)(bx + i) * NIN + by + tx] = __float2half(x);
    }
}

// ============================================================================
// Prep: inputs fp32 [M][K] -> g_A16 fp16 (same layout)
// ============================================================================
__global__ __launch_bounds__(256) void conv_a_kernel(const float* __restrict__ A)
{
    const size_t n4 = (size_t)M_TOTAL * NIN / 4;
    size_t i = (size_t)blockIdx.x * blockDim.x + threadIdx.x;
    const size_t stride = (size_t)gridDim.x * blockDim.x;
    for (; i < n4; i += stride) {
        float4 v = ((const float4*)A)[i];
        ((__half2*)g_A16)[i * 2 + 0] = __floats2half2_rn(v.x, v.y);
        ((__half2*)g_A16)[i * 2 + 1] = __floats2half2_rn(v.z, v.w);
    }
}

// ============================================================================
// Phase 1 GEMM: C[M,N] = A16 @ W16^T + bias  (single-term fp16 HMMA)
// CTA 128m x 256n, 512 thr (16 warps 2x8, warp tile 64x32), K-chunk 64,
// 3 stages, dense 128B rows + XOR swizzle.  (R14 configuration — unchanged.)
// ============================================================================
#define G1A_B    16384
#define G1_STAGE 49152
#define G1_SMEM  147456

__global__ __launch_bounds__(512, 1) void gemm1_kernel(
    const float* __restrict__ bias, float* __restrict__ C)
{
    extern __shared__ char smem[];
    const uint32_t sb0 = smem_u32(smem);
    const int tid  = threadIdx.x;
    const int wid  = tid >> 5;
    const int lane = tid & 31;
    const int m0 = blockIdx.y * 128;
    const int n0 = blockIdx.x * 256;
    const int warp_m = (wid >> 3) * 64;   // 0 or 64
    const int warp_n = (wid & 7) * 32;    // 0..224

    float acc[4][4][4];
#pragma unroll
    for (int i = 0; i < 4; i++)
#pragma unroll
        for (int j = 0; j < 4; j++)
#pragma unroll
            for (int k = 0; k < 4; k++) acc[i][j][k] = 0.f;

    auto issue = [&](int c, int s) {
        const uint32_t st = sb0 + s * G1_STAGE;
        const int kbase = c * 64;
#pragma unroll
        for (int i = 0; i < 6; i++) {
            const int idx = tid + i * 512;
            if (idx < 1024) {
                const int row = idx >> 3, seg = idx & 7;
                CP16(st + sw128(row, seg),
                     g_A16 + (size_t)(m0 + row) * NIN + kbase + seg * 8);
            } else {
                const int j = idx - 1024;
                const int row = j >> 3, seg = j & 7;
                CP16(st + G1A_B + sw128(row, seg),
                     g_Wxh16 + (size_t)(n0 + row) * NIN + kbase + seg * 8);
            }
        }
    };

    issue(0, 0); CP_COMMIT();
    issue(1, 1); CP_COMMIT();

    for (int it = 0; it < 16; it++) {
        CP_WAIT(1);
        __syncthreads();
        if (it + 2 < 16) issue(it + 2, (it + 2) % 3);
        CP_COMMIT();

        const uint32_t st = sb0 + (it % 3) * G1_STAGE;
#pragma unroll
        for (int ks = 0; ks < 4; ks++) {
            uint32_t ah[4][4];
#pragma unroll
            for (int mt = 0; mt < 4; mt++) {
                const int row = warp_m + mt * 16 + (lane & 15);
                const int seg = ks * 2 + (lane >> 4);
                ldsm4(ah[mt], st + sw128(row, seg));
            }
            uint32_t bh[4][2];
#pragma unroll
            for (int g = 0; g < 2; g++) {
                const int row = warp_n + g * 16 + (lane & 7) + ((lane >> 4) << 3);
                const int seg = ks * 2 + ((lane >> 3) & 1);
                uint32_t t[4];
                ldsm4(t, st + G1A_B + sw128(row, seg));
                bh[g * 2][0] = t[0]; bh[g * 2][1] = t[1];
                bh[g * 2 + 1][0] = t[2]; bh[g * 2 + 1][1] = t[3];
            }
#pragma unroll
            for (int mt = 0; mt < 4; mt++)
#pragma unroll
                for (int nt = 0; nt < 4; nt++)
                    mma_f16(acc[mt][nt], ah[mt], bh[nt]);
        }
    }

#pragma unroll
    for (int mt = 0; mt < 4; mt++) {
        const int m = m0 + warp_m + mt * 16 + (lane >> 2);
#pragma unroll
        for (int nt = 0; nt < 4; nt++) {
            const int n = n0 + warp_n + nt * 8 + (lane & 3) * 2;
            const float b0 = bias[n], b1 = bias[n + 1];
            float2 v0 = make_float2(acc[mt][nt][0] + b0, acc[mt][nt][1] + b1);
            float2 v1 = make_float2(acc[mt][nt][2] + b0, acc[mt][nt][3] + b1);
            *(float2*)(C + (size_t)m * NH + n)       = v0;
            *(float2*)(C + (size_t)(m + 8) * NH + n) = v1;
        }
    }
}

// ============================================================================
// t = 0: h0 = tanh(xw[0]); write fp32 out[0] and fp16 state buf 0
// ============================================================================
__global__ __launch_bounds__(256) void tanh0_kernel(float* __restrict__ x)
{
    const size_t i = (size_t)blockIdx.x * blockDim.x + threadIdx.x;  // float4 idx
    float4 v = ((const float4*)x)[i];
    v.x = tanhf(v.x); v.y = tanhf(v.y); v.z = tanhf(v.z); v.w = tanhf(v.w);
    ((float4*)x)[i] = v;
    ((__half2*)g_H16[0])[i * 2 + 0] = __floats2half2_rn(v.x, v.y);
    ((__half2*)g_H16[0])[i * 2 + 1] = __floats2half2_rn(v.z, v.w);
}

// ============================================================================
// Persistent RNN recurrence: t = 1..511.  R14 structure (L2 spin barrier) +
// progressive H waits (4 x 16KB commit groups) + split epilogue (all warps).
// 128 CTAs = 8 m-groups (32 rows) x 16 n-blocks (64 cols), 256 threads.
// W_hh slice (64 rows x 1024 fp16 = 128 KB) resident, dense swizzled rows.
// Split-K across warps (kh = wid>>2); warp tile 16m x 32n.
// smem: W [0,131072) | H [131072,196608) | rbuf [196608,204800)
// ============================================================================
#define PW_BASE  0
#define PH_BASE  131072
#define PR_BASE  196608
#define PK_SMEM  204800

__global__ __launch_bounds__(256, 1) void rnn_persist_kernel(float* __restrict__ out)
{
    extern __shared__ char smem[];
    const uint32_t sb = smem_u32(smem);
    const int tid  = threadIdx.x;
    const int wid  = tid >> 5;
    const int lane = tid & 31;
    const int mb = blockIdx.x >> 4;    // 0..7  (m-group)
    const int nb = blockIdx.x & 15;    // 0..15
    const int m0 = mb * 32;
    const int n0 = nb * 64;
    const int warp_m = (wid & 1) * 16;        // 0 or 16
    const int warp_n = ((wid >> 1) & 1) * 32; // 0 or 32
    const int kh     = wid >> 2;              // k16 half within each k32 sub

    // ---- Load resident W_hh slice: 64 rows x 128 gsegs, swizzled ----
    for (int idx = tid; idx < 8192; idx += 256) {
        const int r    = idx >> 7;        // 0..63
        const int gseg = idx & 127;       // 0..127
        CP16(sb + PW_BASE + swz(r, gseg),
             g_Whh16 + (size_t)(n0 + r) * NH + gseg * 8);
    }
    CP_COMMIT(); CP_WAIT(0); __syncthreads();

    const int hrow = tid >> 3;   // 0..31
    const int hsb  = tid & 7;    // seg base

    for (int t = 1; t < T_STEPS; t++) {
        const __half* Hh = g_H16[(t - 1) & 1];
        __half* HO = g_H16[t & 1];
        float* X = out + (size_t)t * BATCH * NH;

        // ---- Issue the H slice: 4 progressive commit groups of 16 KB ----
        const __half* hsrc = Hh + (size_t)(m0 + hrow) * NH;
        const uint32_t hdst = sb + PH_BASE;
#pragma unroll
        for (int g = 0; g < 4; g++) {
#pragma unroll
            for (int j = 0; j < 4; j++) {
                const int gseg = g * 32 + hsb + j * 8;
                CP16(hdst + swz(hrow, gseg), hsrc + gseg * 8);
            }
            CP_COMMIT();
        }

        // Prefetch this warp's OWN half-rows of the xw tile while H streams
        float2 xwr[4];
        {
            const int mrow = m0 + warp_m + (lane >> 2) + kh * 8;
#pragma unroll
            for (int nt = 0; nt < 4; nt++) {
                const int n = n0 + warp_n + nt * 8 + (lane & 3) * 2;
                xwr[nt] = *(const float2*)(X + (size_t)mrow * NH + n);
            }
        }

        float acc[4][4];
#pragma unroll
        for (int i = 0; i < 4; i++)
#pragma unroll
            for (int j = 0; j < 4; j++) acc[i][j] = 0.f;

        // ---- Compute: subs 8g..8g+7 unlock after commit group g lands ----
        const int arow = warp_m + (lane & 15);
#pragma unroll
        for (int sub = 0; sub < 32; sub++) {
            if (sub == 0)  { CP_WAIT(3); __syncthreads(); }
            if (sub == 8)  { CP_WAIT(2); __syncthreads(); }
            if (sub == 16) { CP_WAIT(1); __syncthreads(); }
            if (sub == 24) { CP_WAIT(0); __syncthreads(); }

            const int gsA = sub * 4 + kh * 2 + (lane >> 4);
            uint32_t ah[4];
            ldsm4(ah, sb + PH_BASE + swz(arow, gsA));

            const int gsB = sub * 4 + kh * 2 + ((lane >> 3) & 1);
            uint32_t bh[4][2];
#pragma unroll
            for (int g = 0; g < 2; g++) {
                const int nr = warp_n + g * 16 + (lane & 7) + ((lane >> 4) << 3);
                uint32_t tmp[4];
                ldsm4(tmp, sb + PW_BASE + swz(nr, gsB));
                bh[g * 2][0] = tmp[0]; bh[g * 2][1] = tmp[1];
                bh[g * 2 + 1][0] = tmp[2]; bh[g * 2 + 1][1] = tmp[3];
            }
#pragma unroll
            for (int nt = 0; nt < 4; nt++) mma_f16(acc[nt], ah, bh[nt]);
        }

        // ---- Exchange the NON-owned half of each warp's accumulators ----
        __syncthreads();
        float* rbuf = (float*)(smem + PR_BASE);   // 32 x 64 fp32 = 8 KB
        {
            const int exh = kh ^ 1;   // the half this warp gives away
            const int m = warp_m + (lane >> 2) + exh * 8;
#pragma unroll
            for (int nt = 0; nt < 4; nt++) {
                const int n = warp_n + nt * 8 + (lane & 3) * 2;
                *(float2*)(rbuf + m * 64 + n) = make_float2(
                    acc[nt][exh * 2 + 0], acc[nt][exh * 2 + 1]);
            }
        }
        __syncthreads();

        // ---- Epilogue (ALL warps): finalize own half (8 rows each) ----
        {
            const int mloc = warp_m + (lane >> 2) + kh * 8;
            const int m = m0 + mloc;
#pragma unroll
            for (int nt = 0; nt < 4; nt++) {
                const int nloc = warp_n + nt * 8 + (lane & 3) * 2;
                const int n = n0 + nloc;
                const size_t off = (size_t)m * NH + n;
                const float2 other = *(const float2*)(rbuf + mloc * 64 + nloc);
                const float s0 = acc[nt][kh * 2 + 0] + other.x;
                const float s1 = acc[nt][kh * 2 + 1] + other.y;
                const float v0 = tanhf(xwr[nt].x + s0);
                const float v1 = tanhf(xwr[nt].y + s1);
                *(float2*)(X + off) = make_float2(v0, v1);
                *(__half2*)(HO + off) = __floats2half2_rn(v0, v1);
                if (t == T_STEPS - 1)
                    *(float2*)(out + (size_t)T_STEPS * BATCH * NH + off) =
                        make_float2(v0, v1);
            }
        }

        // ---- Per-m-group L2 spin barrier between steps (16 CTAs) ----
        __syncthreads();
        if (tid == 0) grid_bar(mb);
        __syncthreads();
    }
}

// ============================================================================
// Launch
// ============================================================================
extern "C" void kernel_launch(void* const* d_in, const int* in_sizes, int n_in,
                              void* d_out, int out_size)
{
    const float* inputs = (const float*)d_in[0];   // [T, B, NIN]
    const float* W_xh   = (const float*)d_in[1];   // [NIN, NH]
    const float* W_hh   = (const float*)d_in[2];   // [NH, NH]
    const float* b_h    = (const float*)d_in[3];   // [NH]
    float* out = (float*)d_out;                    // [T, B, NH] + [B, NH]

    const size_t step_elems = (size_t)BATCH * NH;  // 262144

    static bool attr_set = false;
    if (!attr_set) {
        cudaFuncSetAttribute(gemm1_kernel,
                             cudaFuncAttributeMaxDynamicSharedMemorySize, G1_SMEM);
        cudaFuncSetAttribute(rnn_persist_kernel,
                             cudaFuncAttributeMaxDynamicSharedMemorySize, PK_SMEM);
        attr_set = true;
    }

    // Prep: transpose weights to fp16 [N][K]; convert inputs to fp16
    {
        dim3 grid(NH / 32, NIN / 32);
        conv_w16_kernel<<<grid, 256>>>(W_xh, 0);
        conv_w16_kernel<<<grid, 256>>>(W_hh, 1);
        conv_a_kernel<<<8192, 256>>>(inputs);
    }

    // Phase 1: xw = inputs @ W_xh + b_h  -> out[0..T)
    {
        dim3 grid(NH / 256, M_TOTAL / 128);   // (4, 1024)
        gemm1_kernel<<<grid, 512, G1_SMEM>>>(b_h, out);
    }

    // t = 0
    tanh0_kernel<<<(int)(step_elems / 4 / 256), 256>>>(out);

    // t = 1..T-1 in ONE persistent kernel (also writes final_state tail)
    rnn_persist_kernel<<<PK_CTAS, 256, PK_SMEM>>>(out);
}